// round 3
// baseline (speedup 1.0000x reference)
#include <cuda_runtime.h>
#include <cstdint>

// Problem constants
// R=16, C=256, B=12(==H), E=768, H=12, D=64
// M = R*C*B = 49152 rows for the projection GEMMs.
// Output = concat(out[16,256,12,768], probs[12,12,256,256]) as float32.

#define M_ROWS   49152
#define E_DIM    768
#define HN       144          // H*B
#define RD       1024         // R*D contraction length for attention
#define OUT_ELEMS 37748736    // 16*256*12*768
#define PROBS_ELEMS 9437184   // 144*256*256

// -------- scratch (device globals; no runtime allocation) ----------
__device__ float g_q[HN * 256 * RD];     // [h*12+n][i][r*64+d]
__device__ float g_k[HN * 256 * RD];
__device__ float g_v[HN * 256 * RD];
__device__ float g_s[HN * 256 * 256];    // scores, then probs in-place
__device__ float g_ctx[M_ROWS * E_DIM];  // ctx in (r,i,n,e) layout

// -------- helpers ----------
__device__ __forceinline__ unsigned f2tf(float x) {
    unsigned u;
    asm("cvt.rna.tf32.f32 %0, %1;" : "=r"(u) : "f"(x));
    return u;
}

__device__ __forceinline__ void mma_tf32(float* c, const unsigned* a, const unsigned* b) {
    asm volatile(
        "mma.sync.aligned.m16n8k8.row.col.f32.tf32.tf32.f32 "
        "{%0,%1,%2,%3}, {%4,%5,%6,%7}, {%8,%9}, {%0,%1,%2,%3};"
        : "+f"(c[0]), "+f"(c[1]), "+f"(c[2]), "+f"(c[3])
        : "r"(a[0]), "r"(a[1]), "r"(a[2]), "r"(a[3]), "r"(b[0]), "r"(b[1]));
}

// Stage a 128x16 tile from a row-major matrix (K contiguous) into padded smem,
// converting fp32 -> tf32 (round-to-nearest) on the way.
__device__ __forceinline__ void stage_rm(const float* __restrict__ src, int ld,
                                         int row0, int k0, unsigned (*S)[17], int t) {
    const int r0 = t >> 2;
    const int c4 = (t & 3) * 4;
#pragma unroll
    for (int rr = 0; rr < 128; rr += 64) {
        float4 v = *(const float4*)(src + (size_t)(row0 + r0 + rr) * ld + k0 + c4);
        unsigned* d = &S[r0 + rr][c4];
        d[0] = f2tf(v.x); d[1] = f2tf(v.y); d[2] = f2tf(v.z); d[3] = f2tf(v.w);
    }
}

// Stage a 16x128 tile (contraction along rows of B) into padded smem.
__device__ __forceinline__ void stage_bT(const float* __restrict__ src, int ld,
                                         int k0, int n0, unsigned (*S)[129], int t) {
    const int row = t >> 5;        // 0..7
    const int c4 = (t & 31) * 4;   // 0..124
#pragma unroll
    for (int rr = 0; rr < 16; rr += 8) {
        float4 v = *(const float4*)(src + (size_t)(k0 + row + rr) * ld + n0 + c4);
        unsigned* d = &S[row + rr][c4];
        d[0] = f2tf(v.x); d[1] = f2tf(v.y); d[2] = f2tf(v.z); d[3] = f2tf(v.w);
    }
}

// Compute a BK=16 chunk: both A and B tiles stored [row][k] (k-contiguous).
__device__ __forceinline__ void compute_chunk(const unsigned (*As)[17], const unsigned (*Bs)[17],
                                              float (*acc)[4][4], int lane, int wm, int wn) {
    const int lr = lane >> 2;
    const int lc = lane & 3;
#pragma unroll
    for (int kk = 0; kk < 16; kk += 8) {
        unsigned af[4][4], bf[4][2];
#pragma unroll
        for (int mt = 0; mt < 4; mt++) {
            int row = wm * 64 + mt * 16 + lr;
            af[mt][0] = As[row][kk + lc];
            af[mt][1] = As[row + 8][kk + lc];
            af[mt][2] = As[row][kk + lc + 4];
            af[mt][3] = As[row + 8][kk + lc + 4];
        }
#pragma unroll
        for (int nt = 0; nt < 4; nt++) {
            int row = wn * 32 + nt * 8 + lr;
            bf[nt][0] = Bs[row][kk + lc];
            bf[nt][1] = Bs[row][kk + lc + 4];
        }
#pragma unroll
        for (int mt = 0; mt < 4; mt++)
#pragma unroll
            for (int nt = 0; nt < 4; nt++)
                mma_tf32(acc[mt][nt], af[mt], bf[nt]);
    }
}

// Compute chunk with B stored [k][n] (ctx GEMM: contraction along B rows).
__device__ __forceinline__ void compute_chunk_bT(const unsigned (*As)[17], const unsigned (*Bs)[129],
                                                 float (*acc)[4][4], int lane, int wm, int wn) {
    const int lr = lane >> 2;
    const int lc = lane & 3;
#pragma unroll
    for (int kk = 0; kk < 16; kk += 8) {
        unsigned af[4][4], bf[4][2];
#pragma unroll
        for (int mt = 0; mt < 4; mt++) {
            int row = wm * 64 + mt * 16 + lr;
            af[mt][0] = As[row][kk + lc];
            af[mt][1] = As[row + 8][kk + lc];
            af[mt][2] = As[row][kk + lc + 4];
            af[mt][3] = As[row + 8][kk + lc + 4];
        }
#pragma unroll
        for (int nt = 0; nt < 4; nt++) {
            int col = wn * 32 + nt * 8 + lr;
            bf[nt][0] = Bs[kk + lc][col];
            bf[nt][1] = Bs[kk + lc + 4][col];
        }
#pragma unroll
        for (int mt = 0; mt < 4; mt++)
#pragma unroll
            for (int nt = 0; nt < 4; nt++)
                mma_tf32(acc[mt][nt], af[mt], bf[nt]);
    }
}

// -------------------- Kernel 1: fused QKV projection --------------------
// out[m,e] = (x[m,:] . W_z[e,:] + b_z[e]) * scale_z, scattered into
// buf[(h*12+n)*256 + i][r*64 + d] where m=((r*256+i)*12+n), e=h*64+d.
__global__ __launch_bounds__(256)
void k_qkv(const float* __restrict__ x,
           const float* __restrict__ Wq, const float* __restrict__ bq,
           const float* __restrict__ Wk, const float* __restrict__ bk,
           const float* __restrict__ Wv, const float* __restrict__ bv) {
    const int z = blockIdx.z;
    const float* W    = (z == 0) ? Wq : (z == 1) ? Wk : Wv;
    const float* bias = (z == 0) ? bq : (z == 1) ? bk : bv;
    float* out        = (z == 0) ? g_q : (z == 1) ? g_k : g_v;
    const float scale = (z == 0) ? 0.03125f : 1.0f;  // (D^-0.5)/sqrt(R)

    __shared__ unsigned As[128][17];
    __shared__ unsigned Bs[128][17];

    const int t = threadIdx.x;
    const int lane = t & 31, warp = t >> 5;
    const int wm = warp >> 2, wn = warp & 3;
    const int m0 = blockIdx.x * 128;
    const int n0 = blockIdx.y * 128;

    float acc[4][4][4];
#pragma unroll
    for (int a = 0; a < 4; a++)
#pragma unroll
        for (int b = 0; b < 4; b++)
#pragma unroll
            for (int c = 0; c < 4; c++) acc[a][b][c] = 0.f;

    for (int k0 = 0; k0 < 768; k0 += 16) {
        stage_rm(x, 768, m0, k0, As, t);
        stage_rm(W, 768, n0, k0, Bs, t);
        __syncthreads();
        compute_chunk(As, Bs, acc, lane, wm, wn);
        __syncthreads();
    }

#pragma unroll
    for (int mt = 0; mt < 4; mt++)
#pragma unroll
        for (int nt = 0; nt < 4; nt++)
#pragma unroll
            for (int e = 0; e < 4; e++) {
                int m = m0 + wm * 64 + mt * 16 + (lane >> 2) + ((e >= 2) ? 8 : 0);
                int n = n0 + wn * 32 + nt * 8 + 2 * (lane & 3) + (e & 1);
                int r = m / 3072;
                int rem = m - r * 3072;
                int i = rem / 12;
                int nb = rem - i * 12;
                int h = n >> 6, d = n & 63;
                float v = (acc[mt][nt][e] + bias[n]) * scale;
                out[(size_t)((h * 12 + nb) * 256 + i) * 1024 + (r << 6) + d] = v;
            }
}

// -------------------- Kernel 2: attention scores --------------------
// per hn: S = Q(256x1024) . K(256x1024)^T
__global__ __launch_bounds__(256)
void k_scores() {
    const int hn = blockIdx.z;
    const float* A = g_q + ((size_t)hn << 18);
    const float* B = g_k + ((size_t)hn << 18);

    __shared__ unsigned As[128][17];
    __shared__ unsigned Bs[128][17];

    const int t = threadIdx.x;
    const int lane = t & 31, warp = t >> 5;
    const int wm = warp >> 2, wn = warp & 3;
    const int m0 = blockIdx.x * 128;
    const int n0 = blockIdx.y * 128;

    float acc[4][4][4];
#pragma unroll
    for (int a = 0; a < 4; a++)
#pragma unroll
        for (int b = 0; b < 4; b++)
#pragma unroll
            for (int c = 0; c < 4; c++) acc[a][b][c] = 0.f;

    for (int k0 = 0; k0 < 1024; k0 += 16) {
        stage_rm(A, 1024, m0, k0, As, t);
        stage_rm(B, 1024, n0, k0, Bs, t);
        __syncthreads();
        compute_chunk(As, Bs, acc, lane, wm, wn);
        __syncthreads();
    }

#pragma unroll
    for (int mt = 0; mt < 4; mt++)
#pragma unroll
        for (int nt = 0; nt < 4; nt++)
#pragma unroll
            for (int e = 0; e < 4; e++) {
                int m = m0 + wm * 64 + mt * 16 + (lane >> 2) + ((e >= 2) ? 8 : 0);
                int n = n0 + wn * 32 + nt * 8 + 2 * (lane & 3) + (e & 1);
                g_s[((size_t)hn << 16) + m * 256 + n] = acc[mt][nt][e];
            }
}

// -------------------- Kernel 3: bias + softmax --------------------
// scores[h,n,i,j] += rel_bias[bucket(dist[h,i,j]), n]; softmax over j.
// Writes probs in-place into g_s and into the d_out probs region.
__global__ __launch_bounds__(256)
void k_softmax(const int* __restrict__ dist, const float* __restrict__ rb,
               float* __restrict__ probs_out) {
    const int bx = blockIdx.x;
    const int hn = bx >> 8;
    const int i = bx & 255;
    const int h = hn / 12;
    const int nb = hn - h * 12;
    const int j = threadIdx.x;
    const int lane = j & 31, warp = j >> 5;

    const size_t sidx = ((size_t)hn << 16) + (i << 8) + j;
    float s = g_s[sidx];

    int dd = dist[((h << 8) + i) * 256 + j];
    int a = dd < 0 ? -dd : dd;
    int bucket;
    if (a < 16) {
        bucket = a;
    } else {
        float nf = (float)a;
        float v = logf(nf * 0.0625f) / 8.047189562170502f * 15.0f;
        bucket = 16 + (int)v;   // trunc toward zero (v > 0)
        if (bucket > 31) bucket = 31;
    }
    s += rb[bucket * 12 + nb];

    __shared__ float red[8];

    // block max via warp shuffles
    float m = s;
#pragma unroll
    for (int o = 16; o > 0; o >>= 1)
        m = fmaxf(m, __shfl_xor_sync(0xffffffffu, m, o));
    if (lane == 0) red[warp] = m;
    __syncthreads();
    float mx = red[0];
#pragma unroll
    for (int w = 1; w < 8; w++) mx = fmaxf(mx, red[w]);
    __syncthreads();

    const float e = expf(s - mx);
    float sum = e;
#pragma unroll
    for (int o = 16; o > 0; o >>= 1)
        sum += __shfl_xor_sync(0xffffffffu, sum, o);
    if (lane == 0) red[warp] = sum;
    __syncthreads();
    float tot = red[0];
#pragma unroll
    for (int w = 1; w < 8; w++) tot += red[w];

    const float p = e / tot;
    g_s[sidx] = p;
    if (probs_out) probs_out[sidx] = p;
}

// -------------------- Kernel 4: context --------------------
// per hn: ctx_tile(256x1024) = P(256x256) . V(256x1024), scattered to (r,i,n,e).
__global__ __launch_bounds__(256)
void k_ctx() {
    const int hn = blockIdx.z;
    const float* A = g_s + ((size_t)hn << 16);   // probs, lda=256
    const float* B = g_v + ((size_t)hn << 18);   // [j][rd], ldb=1024

    __shared__ unsigned As[128][17];
    __shared__ unsigned Bs[16][129];

    const int t = threadIdx.x;
    const int lane = t & 31, warp = t >> 5;
    const int wm = warp >> 2, wn = warp & 3;
    const int m0 = blockIdx.x * 128;   // i
    const int n0 = blockIdx.y * 128;   // rd

    float acc[4][4][4];
#pragma unroll
    for (int a = 0; a < 4; a++)
#pragma unroll
        for (int b = 0; b < 4; b++)
#pragma unroll
            for (int c = 0; c < 4; c++) acc[a][b][c] = 0.f;

    for (int k0 = 0; k0 < 256; k0 += 16) {
        stage_rm(A, 256, m0, k0, As, t);
        stage_bT(B, 1024, k0, n0, Bs, t);
        __syncthreads();
        compute_chunk_bT(As, Bs, acc, lane, wm, wn);
        __syncthreads();
    }

    const int h = hn / 12;
    const int nb = hn - h * 12;
#pragma unroll
    for (int mt = 0; mt < 4; mt++)
#pragma unroll
        for (int nt = 0; nt < 4; nt++)
#pragma unroll
            for (int e = 0; e < 4; e++) {
                int i = m0 + wm * 64 + mt * 16 + (lane >> 2) + ((e >= 2) ? 8 : 0);
                int n = n0 + wn * 32 + nt * 8 + 2 * (lane & 3) + (e & 1);  // rd
                int r = n >> 6, d = n & 63;
                g_ctx[(size_t)((r * 256 + i) * 12 + nb) * 768 + h * 64 + d] = acc[mt][nt][e];
            }
}

// -------------------- Kernel 5: output projection --------------------
__global__ __launch_bounds__(256)
void k_out(const float* __restrict__ Wo, const float* __restrict__ bo,
           float* __restrict__ out) {
    __shared__ unsigned As[128][17];
    __shared__ unsigned Bs[128][17];

    const int t = threadIdx.x;
    const int lane = t & 31, warp = t >> 5;
    const int wm = warp >> 2, wn = warp & 3;
    const int m0 = blockIdx.x * 128;
    const int n0 = blockIdx.y * 128;

    float acc[4][4][4];
#pragma unroll
    for (int a = 0; a < 4; a++)
#pragma unroll
        for (int b = 0; b < 4; b++)
#pragma unroll
            for (int c = 0; c < 4; c++) acc[a][b][c] = 0.f;

    for (int k0 = 0; k0 < 768; k0 += 16) {
        stage_rm(g_ctx, 768, m0, k0, As, t);
        stage_rm(Wo, 768, n0, k0, Bs, t);
        __syncthreads();
        compute_chunk(As, Bs, acc, lane, wm, wn);
        __syncthreads();
    }

#pragma unroll
    for (int mt = 0; mt < 4; mt++)
#pragma unroll
        for (int nt = 0; nt < 4; nt++)
#pragma unroll
            for (int e = 0; e < 4; e++) {
                int m = m0 + wm * 64 + mt * 16 + (lane >> 2) + ((e >= 2) ? 8 : 0);
                int n = n0 + wn * 32 + nt * 8 + 2 * (lane & 3) + (e & 1);
                out[(size_t)m * 768 + n] = acc[mt][nt][e] + bo[n];
            }
}

// -------------------- launch --------------------
extern "C" void kernel_launch(void* const* d_in, const int* in_sizes, int n_in,
                              void* d_out, int out_size) {
    const float* x    = (const float*)d_in[0];
    const int*   dist = (const int*)d_in[1];
    const float* Wq   = (const float*)d_in[2];
    const float* bq   = (const float*)d_in[3];
    const float* Wk   = (const float*)d_in[4];
    const float* bk   = (const float*)d_in[5];
    const float* Wv   = (const float*)d_in[6];
    const float* bv   = (const float*)d_in[7];
    const float* Wo   = (const float*)d_in[8];
    const float* bo   = (const float*)d_in[9];
    const float* rb   = (const float*)d_in[10];

    float* out = (float*)d_out;
    float* probs = (out_size >= OUT_ELEMS + PROBS_ELEMS) ? (out + OUT_ELEMS) : nullptr;

    dim3 thr(256);
    k_qkv<<<dim3(384, 6, 3), thr>>>(x, Wq, bq, Wk, bk, Wv, bv);
    k_scores<<<dim3(2, 2, HN), thr>>>();
    k_softmax<<<dim3(HN * 256), thr>>>(dist, rb, probs);
    k_ctx<<<dim3(2, 8, HN), thr>>>();
    k_out<<<dim3(384, 6), thr>>>(Wo, bo, out);
}

// round 8
// speedup vs baseline: 1.2788x; 1.2788x over previous
#include <cuda_runtime.h>
#include <cstdint>

// R=16, C=256, B=12(==H), E=768, H=12, D=64
#define M_ROWS   49152
#define E_DIM    768
#define HN       144
#define RD       1024
#define OUT_ELEMS 37748736
#define PROBS_ELEMS 9437184

// -------- scratch ----------
__device__ float g_q[HN * 256 * RD];
__device__ float g_k[HN * 256 * RD];
__device__ float g_v[HN * 256 * RD];
__device__ float g_s[HN * 256 * 256];
__device__ float g_ctx[M_ROWS * E_DIM];

__device__ __forceinline__ unsigned f2tf(float x) {
    unsigned u;
    asm("cvt.rna.tf32.f32 %0, %1;" : "=r"(u) : "f"(x));
    return u;
}

__device__ __forceinline__ void mma_tf32(float* c, const unsigned* a, const unsigned* b) {
    asm volatile(
        "mma.sync.aligned.m16n8k8.row.col.f32.tf32.tf32.f32 "
        "{%0,%1,%2,%3}, {%4,%5,%6,%7}, {%8,%9}, {%0,%1,%2,%3};"
        : "+f"(c[0]), "+f"(c[1]), "+f"(c[2]), "+f"(c[3])
        : "r"(a[0]), "r"(a[1]), "r"(a[2]), "r"(a[3]), "r"(b[0]), "r"(b[1]));
}

// ===================== fragment-layout staging =====================
// F-layout for a 128x16 tile: word = ((tile16*2 + kt)*32 + lane')*4 + v'
//   tile16=row>>4, r8=(row>>3)&1, lr=row&7, kt=k>>3, kh=(k>>2)&1, lc=k&3
//   lane' = lr*4 + ((lc ^ (lr>>1) ^ tile16)&3)
//   v     = 2*kh + r8;  v' = v ^ (((kt ^ (tile16>>2))&1)<<1)
// 2048 words (8KB) per tile.

// Load 8 floats from row-major source (row = t>>1, k offset (t&1)*8).
__device__ __forceinline__ void ld_rm(const float* __restrict__ src, int ld,
                                      int row0, int k0, int t, float4& f0, float4& f1) {
    const float* p = src + (size_t)(row0 + (t >> 1)) * ld + k0 + (t & 1) * 8;
    f0 = *(const float4*)p;
    f1 = *(const float4*)(p + 4);
}

__device__ __forceinline__ void sts_rm(unsigned* __restrict__ S, int t, float4 f0, float4 f1) {
    const int row = t >> 1;
    const int tile16 = row >> 4, r8 = (row >> 3) & 1, lr = row & 7, kt = t & 1;
    const int base = (tile16 * 2 + kt) * 128;
    const int x = ((lr >> 1) ^ tile16) & 3;
    const int vx = ((kt ^ (tile16 >> 2)) & 1) << 1;
    const float v0[4] = {f0.x, f0.y, f0.z, f0.w};
    const float v1[4] = {f1.x, f1.y, f1.z, f1.w};
#pragma unroll
    for (int j = 0; j < 4; j++) {
        int lane = lr * 4 + ((j ^ x) & 3);
        S[base + lane * 4 + ((0 + r8) ^ vx)] = f2tf(v0[j]);
        S[base + lane * 4 + ((2 + r8) ^ vx)] = f2tf(v1[j]);
    }
}

// Transposed source [k][n]: tile is n(128 "rows") x k(16). Thread reads along n.
__device__ __forceinline__ void ld_tr(const float* __restrict__ src, int ld,
                                      int k0, int n0, int t, float4& f0, float4& f1) {
    const float* p = src + (size_t)(k0 + (t >> 4)) * ld + n0 + (t & 15) * 8;
    f0 = *(const float4*)p;
    f1 = *(const float4*)(p + 4);
}

__device__ __forceinline__ void sts_tr(unsigned* __restrict__ S, int t, float4 f0, float4 f1) {
    const int kl = t >> 4;
    const int tile16 = (t & 15) >> 1, r8 = t & 1;
    const int kt = kl >> 3, kh = (kl >> 2) & 1, lc = kl & 3;
    const int base = (tile16 * 2 + kt) * 128;
    const int vx = ((kt ^ (tile16 >> 2)) & 1) << 1;
    const int v = (2 * kh + r8) ^ vx;
    const float v0[4] = {f0.x, f0.y, f0.z, f0.w};
    const float v1[4] = {f1.x, f1.y, f1.z, f1.w};
#pragma unroll
    for (int s = 0; s < 4; s++) {
        // Rotate element order with tile16 parity so each STS instruction
        // spans both lr parities across the warp -> 32 distinct banks.
        int j = s ^ (tile16 & 1);
        int lr0 = j;          // f0 element j -> n row j
        int lr1 = 4 + j;      // f1 element j -> n row 4+j
        int lane0 = lr0 * 4 + ((lc ^ (lr0 >> 1) ^ tile16) & 3);
        int lane1 = lr1 * 4 + ((lc ^ (lr1 >> 1) ^ tile16) & 3);
        S[base + lane0 * 4 + v] = f2tf(v0[j]);
        S[base + lane1 * 4 + v] = f2tf(v1[j]);
    }
}

// ===================== compute =====================
__device__ __forceinline__ void compute16(const unsigned* __restrict__ SA,
                                          const unsigned* __restrict__ SB,
                                          float (*acc)[4][4], int lane, int wm, int wn) {
#pragma unroll
    for (int kt = 0; kt < 2; kt++) {
        unsigned a[4][4], b[2][4];
#pragma unroll
        for (int mt = 0; mt < 4; mt++) {
            const int t16 = wm * 4 + mt;
            const int lsw = (lane & 28) | ((lane ^ (lane >> 3) ^ t16) & 3);
            const uint4 q = *(const uint4*)(SA + ((t16 * 2 + kt) * 32 + lsw) * 4);
            if ((kt ^ (t16 >> 2)) & 1) { a[mt][0] = q.z; a[mt][1] = q.w; a[mt][2] = q.x; a[mt][3] = q.y; }
            else                       { a[mt][0] = q.x; a[mt][1] = q.y; a[mt][2] = q.z; a[mt][3] = q.w; }
        }
#pragma unroll
        for (int np = 0; np < 2; np++) {
            const int t16 = wn * 2 + np;
            const int lsw = (lane & 28) | ((lane ^ (lane >> 3) ^ t16) & 3);
            const uint4 q = *(const uint4*)(SB + ((t16 * 2 + kt) * 32 + lsw) * 4);
            if ((kt ^ (t16 >> 2)) & 1) { b[np][0] = q.z; b[np][1] = q.w; b[np][2] = q.x; b[np][3] = q.y; }
            else                       { b[np][0] = q.x; b[np][1] = q.y; b[np][2] = q.z; b[np][3] = q.w; }
        }
#pragma unroll
        for (int mt = 0; mt < 4; mt++)
#pragma unroll
            for (int np = 0; np < 2; np++) {
                unsigned b0[2] = {b[np][0], b[np][2]};
                unsigned b1[2] = {b[np][1], b[np][3]};
                mma_tf32(acc[mt][2 * np],     a[mt], b0);
                mma_tf32(acc[mt][2 * np + 1], a[mt], b1);
            }
    }
}

#define ACC_INIT float acc[4][4][4]; \
    _Pragma("unroll") for (int _a = 0; _a < 4; _a++) \
    _Pragma("unroll") for (int _b = 0; _b < 4; _b++) \
    _Pragma("unroll") for (int _c = 0; _c < 4; _c++) acc[_a][_b][_c] = 0.f;

// Double-buffered GEMM mainloop, both operands row-major [row][k].
__device__ __forceinline__ void gemm_rr(const float* __restrict__ A, int lda, int m0,
                                        const float* __restrict__ B, int ldb, int n0,
                                        int kTotal, int t, float (*acc)[4][4],
                                        unsigned* SA, unsigned* SB) {
    const int lane = t & 31, warp = t >> 5, wm = warp >> 2, wn = warp & 3;
    float4 a0, a1, b0, b1;
    ld_rm(A, lda, m0, 0, t, a0, a1);
    ld_rm(B, ldb, n0, 0, t, b0, b1);
    sts_rm(SA, t, a0, a1);
    sts_rm(SB, t, b0, b1);
    __syncthreads();
    const int nc = kTotal >> 4;
    for (int c = 0; c < nc; c++) {
        const int cur = (c & 1) * 2048, nxt = 2048 - cur;
        if (c + 1 < nc) {
            ld_rm(A, lda, m0, (c + 1) * 16, t, a0, a1);
            ld_rm(B, ldb, n0, (c + 1) * 16, t, b0, b1);
        }
        compute16(SA + cur, SB + cur, acc, lane, wm, wn);
        if (c + 1 < nc) {
            sts_rm(SA + nxt, t, a0, a1);
            sts_rm(SB + nxt, t, b0, b1);
        }
        __syncthreads();
    }
}

// B from transposed source [k][n] (ctx: V).
__device__ __forceinline__ void gemm_rt(const float* __restrict__ A, int lda, int m0,
                                        const float* __restrict__ B, int ldb, int n0,
                                        int kTotal, int t, float (*acc)[4][4],
                                        unsigned* SA, unsigned* SB) {
    const int lane = t & 31, warp = t >> 5, wm = warp >> 2, wn = warp & 3;
    float4 a0, a1, b0, b1;
    ld_rm(A, lda, m0, 0, t, a0, a1);
    ld_tr(B, ldb, 0, n0, t, b0, b1);
    sts_rm(SA, t, a0, a1);
    sts_tr(SB, t, b0, b1);
    __syncthreads();
    const int nc = kTotal >> 4;
    for (int c = 0; c < nc; c++) {
        const int cur = (c & 1) * 2048, nxt = 2048 - cur;
        if (c + 1 < nc) {
            ld_rm(A, lda, m0, (c + 1) * 16, t, a0, a1);
            ld_tr(B, ldb, (c + 1) * 16, n0, t, b0, b1);
        }
        compute16(SA + cur, SB + cur, acc, lane, wm, wn);
        if (c + 1 < nc) {
            sts_rm(SA + nxt, t, a0, a1);
            sts_tr(SB + nxt, t, b0, b1);
        }
        __syncthreads();
    }
}

// -------------------- Kernel 1: fused QKV projection --------------------
__global__ __launch_bounds__(256, 2)
void k_qkv(const float* __restrict__ x,
           const float* __restrict__ Wq, const float* __restrict__ bq,
           const float* __restrict__ Wk, const float* __restrict__ bk,
           const float* __restrict__ Wv, const float* __restrict__ bv) {
    const int z = blockIdx.x;                 // fastest: q/k/v share x tile in L2
    const float* W    = (z == 0) ? Wq : (z == 1) ? Wk : Wv;
    const float* bias = (z == 0) ? bq : (z == 1) ? bk : bv;
    float* out        = (z == 0) ? g_q : (z == 1) ? g_k : g_v;
    const float scale = (z == 0) ? 0.03125f : 1.0f;

    __shared__ unsigned SA[2 * 2048];
    __shared__ unsigned SB[2 * 2048];

    const int t = threadIdx.x;
    const int lane = t & 31, warp = t >> 5, wm = warp >> 2, wn = warp & 3;
    const int n0 = blockIdx.y * 128;
    const int m0 = blockIdx.z * 128;

    ACC_INIT
    gemm_rr(x, 768, m0, W, 768, n0, 768, t, acc, SA, SB);

#pragma unroll
    for (int mt = 0; mt < 4; mt++)
#pragma unroll
        for (int nt = 0; nt < 4; nt++)
#pragma unroll
            for (int e = 0; e < 4; e++) {
                int m = m0 + wm * 64 + mt * 16 + (lane >> 2) + ((e >= 2) ? 8 : 0);
                int n = n0 + wn * 32 + nt * 8 + 2 * (lane & 3) + (e & 1);
                int r = m / 3072;
                int rem = m - r * 3072;
                int i = rem / 12;
                int nb = rem - i * 12;
                int h = n >> 6, d = n & 63;
                float v = (acc[mt][nt][e] + bias[n]) * scale;
                out[(size_t)((h * 12 + nb) * 256 + i) * 1024 + (r << 6) + d] = v;
            }
}

// -------------------- Kernel 2: attention scores --------------------
__global__ __launch_bounds__(256, 2)
void k_scores() {
    const int hn = blockIdx.z;
    const float* A = g_q + ((size_t)hn << 18);
    const float* B = g_k + ((size_t)hn << 18);

    __shared__ unsigned SA[2 * 2048];
    __shared__ unsigned SB[2 * 2048];

    const int t = threadIdx.x;
    const int lane = t & 31, warp = t >> 5, wm = warp >> 2, wn = warp & 3;
    const int m0 = blockIdx.x * 128;
    const int n0 = blockIdx.y * 128;

    ACC_INIT
    gemm_rr(A, 1024, m0, B, 1024, n0, 1024, t, acc, SA, SB);

#pragma unroll
    for (int mt = 0; mt < 4; mt++)
#pragma unroll
        for (int nt = 0; nt < 4; nt++)
#pragma unroll
            for (int e = 0; e < 4; e++) {
                int m = m0 + wm * 64 + mt * 16 + (lane >> 2) + ((e >= 2) ? 8 : 0);
                int n = n0 + wn * 32 + nt * 8 + 2 * (lane & 3) + (e & 1);
                g_s[((size_t)hn << 16) + m * 256 + n] = acc[mt][nt][e];
            }
}

// -------------------- Kernel 3: bias + softmax --------------------
__global__ __launch_bounds__(256)
void k_softmax(const int* __restrict__ dist, const float* __restrict__ rb,
               float* __restrict__ probs_out) {
    const int bx = blockIdx.x;
    const int hn = bx >> 8;
    const int i = bx & 255;
    const int h = hn / 12;
    const int nb = hn - h * 12;
    const int j = threadIdx.x;
    const int lane = j & 31, warp = j >> 5;

    const size_t sidx = ((size_t)hn << 16) + (i << 8) + j;
    float s = g_s[sidx];

    int dd = dist[((h << 8) + i) * 256 + j];
    int a = dd < 0 ? -dd : dd;
    int bucket;
    if (a < 16) {
        bucket = a;
    } else {
        float nf = (float)a;
        float v = logf(nf * 0.0625f) / 8.047189562170502f * 15.0f;
        bucket = 16 + (int)v;
        if (bucket > 31) bucket = 31;
    }
    s += rb[bucket * 12 + nb];

    __shared__ float red[8];
    float m = s;
#pragma unroll
    for (int o = 16; o > 0; o >>= 1)
        m = fmaxf(m, __shfl_xor_sync(0xffffffffu, m, o));
    if (lane == 0) red[warp] = m;
    __syncthreads();
    float mx = red[0];
#pragma unroll
    for (int w = 1; w < 8; w++) mx = fmaxf(mx, red[w]);
    __syncthreads();

    const float e = expf(s - mx);
    float sum = e;
#pragma unroll
    for (int o = 16; o > 0; o >>= 1)
        sum += __shfl_xor_sync(0xffffffffu, sum, o);
    if (lane == 0) red[warp] = sum;
    __syncthreads();
    float tot = red[0];
#pragma unroll
    for (int w = 1; w < 8; w++) tot += red[w];

    const float p = e / tot;
    g_s[sidx] = p;
    if (probs_out) probs_out[sidx] = p;
}

// -------------------- Kernel 4: context --------------------
__global__ __launch_bounds__(256, 2)
void k_ctx() {
    const int hn = blockIdx.z;
    const float* A = g_s + ((size_t)hn << 16);   // probs [i][j], lda=256
    const float* B = g_v + ((size_t)hn << 18);   // [j][rd], ldb=1024 (transposed source)

    __shared__ unsigned SA[2 * 2048];
    __shared__ unsigned SB[2 * 2048];

    const int t = threadIdx.x;
    const int lane = t & 31, warp = t >> 5, wm = warp >> 2, wn = warp & 3;
    const int m0 = blockIdx.x * 128;   // i
    const int n0 = blockIdx.y * 128;   // rd

    ACC_INIT
    gemm_rt(A, 256, m0, B, 1024, n0, 256, t, acc, SA, SB);

    const int h = hn / 12;
    const int nb = hn - h * 12;
#pragma unroll
    for (int mt = 0; mt < 4; mt++)
#pragma unroll
        for (int nt = 0; nt < 4; nt++)
#pragma unroll
            for (int e = 0; e < 4; e++) {
                int i = m0 + wm * 64 + mt * 16 + (lane >> 2) + ((e >= 2) ? 8 : 0);
                int n = n0 + wn * 32 + nt * 8 + 2 * (lane & 3) + (e & 1);
                int r = n >> 6, d = n & 63;
                g_ctx[(size_t)((r * 256 + i) * 12 + nb) * 768 + h * 64 + d] = acc[mt][nt][e];
            }
}

// -------------------- Kernel 5: output projection --------------------
__global__ __launch_bounds__(256, 2)
void k_out(const float* __restrict__ Wo, const float* __restrict__ bo,
           float* __restrict__ out) {
    __shared__ unsigned SA[2 * 2048];
    __shared__ unsigned SB[2 * 2048];

    const int t = threadIdx.x;
    const int lane = t & 31, warp = t >> 5, wm = warp >> 2, wn = warp & 3;
    const int n0 = blockIdx.x * 128;   // n fastest: m-tile of ctx shared in L2
    const int m0 = blockIdx.y * 128;

    ACC_INIT
    gemm_rr(g_ctx, 768, m0, Wo, 768, n0, 768, t, acc, SA, SB);

#pragma unroll
    for (int mt = 0; mt < 4; mt++)
#pragma unroll
        for (int nt = 0; nt < 4; nt++)
#pragma unroll
            for (int e = 0; e < 4; e++) {
                int m = m0 + wm * 64 + mt * 16 + (lane >> 2) + ((e >= 2) ? 8 : 0);
                int n = n0 + wn * 32 + nt * 8 + 2 * (lane & 3) + (e & 1);
                out[(size_t)m * 768 + n] = acc[mt][nt][e] + bo[n];
            }
}

// -------------------- launch --------------------
extern "C" void kernel_launch(void* const* d_in, const int* in_sizes, int n_in,
                              void* d_out, int out_size) {
    const float* x    = (const float*)d_in[0];
    const int*   dist = (const int*)d_in[1];
    const float* Wq   = (const float*)d_in[2];
    const float* bq   = (const float*)d_in[3];
    const float* Wk   = (const float*)d_in[4];
    const float* bk   = (const float*)d_in[5];
    const float* Wv   = (const float*)d_in[6];
    const float* bv   = (const float*)d_in[7];
    const float* Wo   = (const float*)d_in[8];
    const float* bo   = (const float*)d_in[9];
    const float* rb   = (const float*)d_in[10];

    float* out = (float*)d_out;
    float* probs = (out_size >= OUT_ELEMS + PROBS_ELEMS) ? (out + OUT_ELEMS) : nullptr;

    dim3 thr(256);
    k_qkv<<<dim3(3, 6, 384), thr>>>(x, Wq, bq, Wk, bk, Wv, bv);
    k_scores<<<dim3(2, 2, HN), thr>>>();
    k_softmax<<<dim3(HN * 256), thr>>>(dist, rb, probs);
    k_ctx<<<dim3(2, 8, HN), thr>>>();
    k_out<<<dim3(6, 384), thr>>>(Wo, bo, out);
}

// round 10
// speedup vs baseline: 1.4445x; 1.1296x over previous
#include <cuda_runtime.h>
#include <cstdint>

// R=16, C=256, B=12(==H), E=768, H=12, D=64
#define HN       144
#define OUT_ELEMS 37748736
#define PROBS_ELEMS 9437184

// ===== scratch: all GEMM operands stored as tf32 words in fragment "F-tile" layout =====
// F-tile = 2048 words for a (128 row x 16 k) tile:
//   t16=row>>4, r8=(row>>3)&1, lr=row&7 ; kt=k>>3, kh=(k>>2)&1, lc=k&3
//   lane' = lr*4 + ((lc ^ (lr>>1) ^ t16)&3)
//   v'    = (2*kh + r8) ^ (((kt ^ (t16&1))&1)<<1)
//   word  = (t16*2+kt)*128 + lane'*4 + v'
__device__ unsigned g_x_f[37748736];   // x     [mtile384][kc48][2048]
__device__ unsigned g_w_f[2359296];    // Wq/Wk/Wv/Wo [z*6+ntile][kc48][2048]
__device__ unsigned g_q_f[37748736];   // q     [hn*2+itile][kc64][2048]
__device__ unsigned g_k_f[37748736];   // k     [hn*2+jtile][kc64][2048]
__device__ unsigned g_v_f[37748736];   // v     [hn*8+rdtile][kc16][2048]
__device__ float    g_s[9437184];      // scores row-major [hn][i][j]
__device__ unsigned g_p_f[9437184];    // probs [hn*2+itile][kc16][2048]
__device__ unsigned g_ctx_f[37748736]; // ctx   [mtile384][kc48][2048]

__device__ __forceinline__ unsigned f2tf(float x) {
    unsigned u;
    asm("cvt.rna.tf32.f32 %0, %1;" : "=r"(u) : "f"(x));
    return u;
}

__device__ __forceinline__ void mma_tf32(float* c, const unsigned* a, const unsigned* b) {
    asm volatile(
        "mma.sync.aligned.m16n8k8.row.col.f32.tf32.tf32.f32 "
        "{%0,%1,%2,%3}, {%4,%5,%6,%7}, {%8,%9}, {%0,%1,%2,%3};"
        : "+f"(c[0]), "+f"(c[1]), "+f"(c[2]), "+f"(c[3])
        : "r"(a[0]), "r"(a[1]), "r"(a[2]), "r"(a[3]), "r"(b[0]), "r"(b[1]));
}

// word index inside an F-tile for (row 0..127, k 0..15)
__device__ __forceinline__ int fword(int row, int k) {
    int t16 = row >> 4, r8 = (row >> 3) & 1, lr = row & 7;
    int kt = k >> 3, kh = (k >> 2) & 1, lc = k & 3;
    int lane = lr * 4 + ((lc ^ (lr >> 1) ^ t16) & 3);
    int v = (2 * kh + r8) ^ (((kt ^ (t16 & 1)) & 1) << 1);
    return (t16 * 2 + kt) * 128 + lane * 4 + v;
}

// ===================== compute =====================
// oA[mt] = (wm*4+mt)*256 + lswA*4 ; oB[np] = (wn*2+np)*256 + lswB*4 (precomputed).
// Register-half swap is compile-time: (kt^mt)&1 / (kt^np)&1.
__device__ __forceinline__ void compute16(const unsigned* __restrict__ SA,
                                          const unsigned* __restrict__ SB,
                                          float (*acc)[4][4],
                                          const int* __restrict__ oA,
                                          const int* __restrict__ oB) {
#pragma unroll
    for (int kt = 0; kt < 2; kt++) {
        unsigned a[4][4], b[2][4];
#pragma unroll
        for (int mt = 0; mt < 4; mt++) {
            const uint4 q = *(const uint4*)(SA + oA[mt] + kt * 128);
            if ((kt ^ mt) & 1) { a[mt][0] = q.z; a[mt][1] = q.w; a[mt][2] = q.x; a[mt][3] = q.y; }
            else               { a[mt][0] = q.x; a[mt][1] = q.y; a[mt][2] = q.z; a[mt][3] = q.w; }
        }
#pragma unroll
        for (int np = 0; np < 2; np++) {
            const uint4 q = *(const uint4*)(SB + oB[np] + kt * 128);
            if ((kt ^ np) & 1) { b[np][0] = q.z; b[np][1] = q.w; b[np][2] = q.x; b[np][3] = q.y; }
            else               { b[np][0] = q.x; b[np][1] = q.y; b[np][2] = q.z; b[np][3] = q.w; }
        }
#pragma unroll
        for (int mt = 0; mt < 4; mt++)
#pragma unroll
            for (int np = 0; np < 2; np++) {
                unsigned b0[2] = {b[np][0], b[np][2]};
                unsigned b1[2] = {b[np][1], b[np][3]};
                mma_tf32(acc[mt][2 * np],     a[mt], b0);
                mma_tf32(acc[mt][2 * np + 1], a[mt], b1);
            }
    }
}

#define ACC_INIT float acc[4][4][4]; \
    _Pragma("unroll") for (int _a = 0; _a < 4; _a++) \
    _Pragma("unroll") for (int _b = 0; _b < 4; _b++) \
    _Pragma("unroll") for (int _c = 0; _c < 4; _c++) acc[_a][_b][_c] = 0.f;

#define PREP_OFFS int oA[4], oB[2]; \
    _Pragma("unroll") for (int _m = 0; _m < 4; _m++) { \
        int _l = (lane & 28) | ((lane ^ (lane >> 3) ^ _m) & 3); \
        oA[_m] = (wm * 4 + _m) * 256 + _l * 4; } \
    _Pragma("unroll") for (int _n = 0; _n < 2; _n++) { \
        int _l = (lane & 28) | ((lane ^ (lane >> 3) ^ ((wn & 1) * 2 + _n)) & 3); \
        oB[_n] = (wn * 2 + _n) * 256 + _l * 4; }

// Double-buffered mainloop over pre-staged F-tiles: pure uint4 copies.
__device__ __forceinline__ void gemm_f(const unsigned* __restrict__ A,
                                       const unsigned* __restrict__ B,
                                       int nk, int t, float (*acc)[4][4],
                                       unsigned* SA, unsigned* SB,
                                       const int* oA, const int* oB) {
    const int w8 = t * 8;
    uint4 pa0 = *(const uint4*)(A + w8);
    uint4 pa1 = *(const uint4*)(A + w8 + 4);
    uint4 pb0 = *(const uint4*)(B + w8);
    uint4 pb1 = *(const uint4*)(B + w8 + 4);
    *(uint4*)(SA + w8) = pa0; *(uint4*)(SA + w8 + 4) = pa1;
    *(uint4*)(SB + w8) = pb0; *(uint4*)(SB + w8 + 4) = pb1;
    __syncthreads();
    for (int c = 0; c < nk; c++) {
        const int cur = (c & 1) * 2048, nxt = 2048 - cur;
        if (c + 1 < nk) {
            const unsigned* An = A + (c + 1) * 2048 + w8;
            const unsigned* Bn = B + (c + 1) * 2048 + w8;
            pa0 = *(const uint4*)An; pa1 = *(const uint4*)(An + 4);
            pb0 = *(const uint4*)Bn; pb1 = *(const uint4*)(Bn + 4);
        }
        compute16(SA + cur, SB + cur, acc, oA, oB);
        if (c + 1 < nk) {
            *(uint4*)(SA + nxt + w8) = pa0; *(uint4*)(SA + nxt + w8 + 4) = pa1;
            *(uint4*)(SB + nxt + w8) = pb0; *(uint4*)(SB + nxt + w8 + 4) = pb1;
        }
        __syncthreads();
    }
}

// -------------------- Kernel 0: convert x / W's into F-layout tf32 --------------------
__global__ __launch_bounds__(256)
void k_prep(const float* __restrict__ x,
            const float* __restrict__ Wq, const float* __restrict__ Wk,
            const float* __restrict__ Wv, const float* __restrict__ Wo) {
    const int bb = blockIdx.x;
    const float* src;
    unsigned* dst;
    int row0, k0;
    if (bb < 18432) {                       // x: mtile(384) x kc(48)
        int mtile = bb / 48, kc = bb - mtile * 48;
        src = x; row0 = mtile * 128; k0 = kc * 16;
        dst = g_x_f + (size_t)bb * 2048;
    } else {                                // W: z(4) x ntile(6) x kc(48)
        int b2 = bb - 18432;
        int z = b2 / 288, rem = b2 - z * 288;
        int ntile = rem / 48, kc = rem - ntile * 48;
        src = (z == 0) ? Wq : (z == 1) ? Wk : (z == 2) ? Wv : Wo;
        row0 = ntile * 128; k0 = kc * 16;
        dst = g_w_f + (size_t)b2 * 2048;
    }
    const int t = threadIdx.x;
    const int row = t >> 1, kt = t & 1;
    const float* p = src + (size_t)(row0 + row) * 768 + k0 + kt * 8;
    float4 f0 = *(const float4*)p, f1 = *(const float4*)(p + 4);
    const int t16 = row >> 4, r8 = (row >> 3) & 1, lr = row & 7;
    const int base = (t16 * 2 + kt) * 128;
    const int vx = ((kt ^ (t16 & 1)) & 1) << 1;
    const float e0[4] = {f0.x, f0.y, f0.z, f0.w};
    const float e1[4] = {f1.x, f1.y, f1.z, f1.w};
#pragma unroll
    for (int j = 0; j < 4; j++) {
        int lane = lr * 4 + ((j ^ (lr >> 1) ^ t16) & 3);
        dst[base + lane * 4 + ((0 + r8) ^ vx)] = f2tf(e0[j]);
        dst[base + lane * 4 + ((2 + r8) ^ vx)] = f2tf(e1[j]);
    }
}

// -------------------- Kernel 1: fused QKV projection --------------------
__global__ __launch_bounds__(256, 2)
void k_qkv(const float* __restrict__ bq, const float* __restrict__ bk,
           const float* __restrict__ bv) {
    const int z = blockIdx.x;
    const float* bias = (z == 0) ? bq : (z == 1) ? bk : bv;
    unsigned* out     = (z == 0) ? g_q_f : (z == 1) ? g_k_f : g_v_f;
    const float scale = (z == 0) ? 0.03125f : 1.0f;

    __shared__ unsigned SA[2 * 2048];
    __shared__ unsigned SB[2 * 2048];

    const int t = threadIdx.x;
    const int lane = t & 31, warp = t >> 5, wm = warp >> 2, wn = warp & 3;
    const int n0 = blockIdx.y * 128;
    const int m0 = blockIdx.z * 128;

    const unsigned* A = g_x_f + (size_t)blockIdx.z * 48 * 2048;
    const unsigned* B = g_w_f + (size_t)((z * 6 + blockIdx.y) * 48) * 2048;

    PREP_OFFS
    ACC_INIT
    gemm_f(A, B, 48, t, acc, SA, SB, oA, oB);

#pragma unroll
    for (int mt = 0; mt < 4; mt++)
#pragma unroll
        for (int nt = 0; nt < 4; nt++)
#pragma unroll
            for (int e = 0; e < 4; e++) {
                int m = m0 + wm * 64 + mt * 16 + (lane >> 2) + ((e >= 2) ? 8 : 0);
                int n = n0 + wn * 32 + nt * 8 + 2 * (lane & 3) + (e & 1);
                int r = m / 3072;
                int rem = m - r * 3072;
                int i = rem / 12;
                int nb = rem - i * 12;
                int h = n >> 6, d = n & 63;
                int hn = h * 12 + nb;
                unsigned w = f2tf((acc[mt][nt][e] + bias[n]) * scale);
                size_t idx;
                if (z < 2)   // q/k: rows=i, k=rd
                    idx = ((size_t)(hn * 2 + (i >> 7)) * 64 + (r * 4 + (d >> 4))) * 2048
                        + fword(i & 127, d & 15);
                else         // v: rows=rd, k=i
                    idx = ((size_t)(hn * 8 + (r >> 1)) * 16 + (i >> 4)) * 2048
                        + fword(((r & 1) << 6) | d, i & 15);
                out[idx] = w;
            }
}

// -------------------- Kernel 2: attention scores --------------------
__global__ __launch_bounds__(256, 2)
void k_scores() {
    const int hn = blockIdx.z;
    const unsigned* A = g_q_f + (size_t)(hn * 2 + blockIdx.x) * 64 * 2048;
    const unsigned* B = g_k_f + (size_t)(hn * 2 + blockIdx.y) * 64 * 2048;

    __shared__ unsigned SA[2 * 2048];
    __shared__ unsigned SB[2 * 2048];

    const int t = threadIdx.x;
    const int lane = t & 31, warp = t >> 5, wm = warp >> 2, wn = warp & 3;
    const int m0 = blockIdx.x * 128;
    const int n0 = blockIdx.y * 128;

    PREP_OFFS
    ACC_INIT
    gemm_f(A, B, 64, t, acc, SA, SB, oA, oB);

#pragma unroll
    for (int mt = 0; mt < 4; mt++)
#pragma unroll
        for (int nt = 0; nt < 4; nt++)
#pragma unroll
            for (int e = 0; e < 4; e++) {
                int m = m0 + wm * 64 + mt * 16 + (lane >> 2) + ((e >= 2) ? 8 : 0);
                int n = n0 + wn * 32 + nt * 8 + 2 * (lane & 3) + (e & 1);
                g_s[((size_t)hn << 16) + m * 256 + n] = acc[mt][nt][e];
            }
}

// -------------------- Kernel 3: bias + softmax --------------------
__global__ __launch_bounds__(256)
void k_softmax(const int* __restrict__ dist, const float* __restrict__ rb,
               float* __restrict__ probs_out) {
    const int bx = blockIdx.x;
    const int hn = bx >> 8;
    const int i = bx & 255;
    const int h = hn / 12;
    const int nb = hn - h * 12;
    const int j = threadIdx.x;
    const int lane = j & 31, warp = j >> 5;

    const size_t sidx = ((size_t)hn << 16) + (i << 8) + j;
    float s = g_s[sidx];

    int dd = dist[((h << 8) + i) * 256 + j];
    int a = dd < 0 ? -dd : dd;
    int bucket;
    if (a < 16) {
        bucket = a;
    } else {
        float nf = (float)a;
        float v = logf(nf * 0.0625f) / 8.047189562170502f * 15.0f;
        bucket = 16 + (int)v;
        if (bucket > 31) bucket = 31;
    }
    s += rb[bucket * 12 + nb];

    __shared__ float red[8];
    float m = s;
#pragma unroll
    for (int o = 16; o > 0; o >>= 1)
        m = fmaxf(m, __shfl_xor_sync(0xffffffffu, m, o));
    if (lane == 0) red[warp] = m;
    __syncthreads();
    float mx = red[0];
#pragma unroll
    for (int w = 1; w < 8; w++) mx = fmaxf(mx, red[w]);
    __syncthreads();

    const float e = expf(s - mx);
    float sum = e;
#pragma unroll
    for (int o = 16; o > 0; o >>= 1)
        sum += __shfl_xor_sync(0xffffffffu, sum, o);
    if (lane == 0) red[warp] = sum;
    __syncthreads();
    float tot = red[0];
#pragma unroll
    for (int w = 1; w < 8; w++) tot += red[w];

    const float p = e / tot;
    if (probs_out) probs_out[sidx] = p;
    g_p_f[((size_t)(hn * 2 + (i >> 7)) * 16 + (j >> 4)) * 2048 + fword(i & 127, j & 15)] = f2tf(p);
}

// -------------------- Kernel 4: context --------------------
__global__ __launch_bounds__(256, 2)
void k_ctx() {
    const int hn = blockIdx.z;
    const unsigned* A = g_p_f + (size_t)(hn * 2 + blockIdx.x) * 16 * 2048;
    const unsigned* B = g_v_f + (size_t)(hn * 8 + blockIdx.y) * 16 * 2048;

    __shared__ unsigned SA[2 * 2048];
    __shared__ unsigned SB[2 * 2048];

    const int t = threadIdx.x;
    const int lane = t & 31, warp = t >> 5, wm = warp >> 2, wn = warp & 3;
    const int m0 = blockIdx.x * 128;   // i
    const int n0 = blockIdx.y * 128;   // rd

    PREP_OFFS
    ACC_INIT
    gemm_f(A, B, 16, t, acc, SA, SB, oA, oB);

    const int h = hn / 12;
    const int nb = hn - h * 12;
#pragma unroll
    for (int mt = 0; mt < 4; mt++)
#pragma unroll
        for (int nt = 0; nt < 4; nt++)
#pragma unroll
            for (int e = 0; e < 4; e++) {
                int i = m0 + wm * 64 + mt * 16 + (lane >> 2) + ((e >= 2) ? 8 : 0);
                int n = n0 + wn * 32 + nt * 8 + 2 * (lane & 3) + (e & 1);  // rd
                int r = n >> 6, d = n & 63;
                int mo = (r * 256 + i) * 12 + nb;
                int ec = h * 64 + d;
                g_ctx_f[((size_t)(mo >> 7) * 48 + (ec >> 4)) * 2048 + fword(mo & 127, d & 15)]
                    = f2tf(acc[mt][nt][e]);
            }
}

// -------------------- Kernel 5: output projection --------------------
__global__ __launch_bounds__(256, 2)
void k_out(const float* __restrict__ bo, float* __restrict__ out) {
    __shared__ unsigned SA[2 * 2048];
    __shared__ unsigned SB[2 * 2048];

    const int t = threadIdx.x;
    const int lane = t & 31, warp = t >> 5, wm = warp >> 2, wn = warp & 3;
    const int n0 = blockIdx.x * 128;
    const int m0 = blockIdx.y * 128;

    const unsigned* A = g_ctx_f + (size_t)blockIdx.y * 48 * 2048;
    const unsigned* B = g_w_f + (size_t)((3 * 6 + blockIdx.x) * 48) * 2048;

    PREP_OFFS
    ACC_INIT
    gemm_f(A, B, 48, t, acc, SA, SB, oA, oB);

#pragma unroll
    for (int mt = 0; mt < 4; mt++)
#pragma unroll
        for (int nt = 0; nt < 4; nt++)
#pragma unroll
            for (int e = 0; e < 4; e++) {
                int m = m0 + wm * 64 + mt * 16 + (lane >> 2) + ((e >= 2) ? 8 : 0);
                int n = n0 + wn * 32 + nt * 8 + 2 * (lane & 3) + (e & 1);
                out[(size_t)m * 768 + n] = acc[mt][nt][e] + bo[n];
            }
}

// -------------------- launch --------------------
extern "C" void kernel_launch(void* const* d_in, const int* in_sizes, int n_in,
                              void* d_out, int out_size) {
    const float* x    = (const float*)d_in[0];
    const int*   dist = (const int*)d_in[1];
    const float* Wq   = (const float*)d_in[2];
    const float* bq   = (const float*)d_in[3];
    const float* Wk   = (const float*)d_in[4];
    const float* bk   = (const float*)d_in[5];
    const float* Wv   = (const float*)d_in[6];
    const float* bv   = (const float*)d_in[7];
    const float* Wo   = (const float*)d_in[8];
    const float* bo   = (const float*)d_in[9];
    const float* rb   = (const float*)d_in[10];

    float* out = (float*)d_out;
    float* probs = (out_size >= OUT_ELEMS + PROBS_ELEMS) ? (out + OUT_ELEMS) : nullptr;

    dim3 thr(256);
    k_prep<<<dim3(18432 + 1152), thr>>>(x, Wq, Wk, Wv, Wo);
    k_qkv<<<dim3(3, 6, 384), thr>>>(bq, bk, bv);
    k_scores<<<dim3(2, 2, HN), thr>>>();
    k_softmax<<<dim3(HN * 256), thr>>>(dist, rb, probs);
    k_ctx<<<dim3(2, 8, HN), thr>>>();
    k_out<<<dim3(6, 384), thr>>>(bo, out);
}

// round 14
// speedup vs baseline: 1.6496x; 1.1420x over previous
#include <cuda_runtime.h>
#include <cstdint>

// R=16, C=256, B=12(==H), E=768, H=12, D=64
#define HN       144
#define OUT_ELEMS 37748736
#define PROBS_ELEMS 9437184

// ===== scratch: all GEMM operands stored as tf32 words in fragment "F-tile" layout =====
// F-tile = 2048 words for a (128 row x 16 k) tile:
//   t16=row>>4, r8=(row>>3)&1, lr=row&7 ; kt=k>>3, kh=(k>>2)&1, lc=k&3
//   lane' = lr*4 + ((lc ^ (lr>>1) ^ t16)&3)
//   v'    = (2*kh + r8) ^ (((kt ^ (t16&1))&1)<<1)
//   word  = (t16*2+kt)*128 + lane'*4 + v'
__device__ unsigned g_x_f[37748736];   // x     [mtile384][kc48][2048]
__device__ unsigned g_w_f[2359296];    // Wq/Wk/Wv/Wo [z*6+ntile][kc48][2048]
__device__ unsigned g_q_f[37748736];   // q     [hn*2+itile][kc64][2048]
__device__ unsigned g_k_f[37748736];   // k     [hn*2+jtile][kc64][2048]
__device__ unsigned g_v_f[37748736];   // v     [hn*8+rdtile][kc16][2048]
__device__ float    g_s[9437184];      // scores row-major [hn][i][j]
__device__ unsigned g_p_f[9437184];    // probs [hn*2+itile][kc16][2048]
__device__ unsigned g_ctx_f[37748736]; // ctx   [mtile384][kc48][2048]

__device__ __forceinline__ unsigned f2tf(float x) {
    unsigned u;
    asm("cvt.rna.tf32.f32 %0, %1;" : "=r"(u) : "f"(x));
    return u;
}

__device__ __forceinline__ void mma_tf32(float* c, const unsigned* a, const unsigned* b) {
    asm volatile(
        "mma.sync.aligned.m16n8k8.row.col.f32.tf32.tf32.f32 "
        "{%0,%1,%2,%3}, {%4,%5,%6,%7}, {%8,%9}, {%0,%1,%2,%3};"
        : "+f"(c[0]), "+f"(c[1]), "+f"(c[2]), "+f"(c[3])
        : "r"(a[0]), "r"(a[1]), "r"(a[2]), "r"(a[3]), "r"(b[0]), "r"(b[1]));
}

__device__ __forceinline__ void cp_async16(unsigned* dst, const unsigned* src) {
    unsigned saddr = (unsigned)__cvta_generic_to_shared(dst);
    asm volatile("cp.async.cg.shared.global [%0], [%1], 16;" :: "r"(saddr), "l"(src));
}
__device__ __forceinline__ void cp_commit() {
    asm volatile("cp.async.commit_group;");
}
__device__ __forceinline__ void cp_wait1() {
    asm volatile("cp.async.wait_group 1;");
}

// word index inside an F-tile for (row 0..127, k 0..15)
__device__ __forceinline__ int fword(int row, int k) {
    int t16 = row >> 4, r8 = (row >> 3) & 1, lr = row & 7;
    int kt = k >> 3, kh = (k >> 2) & 1, lc = k & 3;
    int lane = lr * 4 + ((lc ^ (lr >> 1) ^ t16) & 3);
    int v = (2 * kh + r8) ^ (((kt ^ (t16 & 1)) & 1) << 1);
    return (t16 * 2 + kt) * 128 + lane * 4 + v;
}

// ===================== compute =====================
__device__ __forceinline__ void compute16(const unsigned* __restrict__ SA,
                                          const unsigned* __restrict__ SB,
                                          float (*acc)[4][4],
                                          const int* __restrict__ oA,
                                          const int* __restrict__ oB) {
#pragma unroll
    for (int kt = 0; kt < 2; kt++) {
        unsigned a[4][4], b[2][4];
#pragma unroll
        for (int mt = 0; mt < 4; mt++) {
            const uint4 q = *(const uint4*)(SA + oA[mt] + kt * 128);
            if ((kt ^ mt) & 1) { a[mt][0] = q.z; a[mt][1] = q.w; a[mt][2] = q.x; a[mt][3] = q.y; }
            else               { a[mt][0] = q.x; a[mt][1] = q.y; a[mt][2] = q.z; a[mt][3] = q.w; }
        }
#pragma unroll
        for (int np = 0; np < 2; np++) {
            const uint4 q = *(const uint4*)(SB + oB[np] + kt * 128);
            if ((kt ^ np) & 1) { b[np][0] = q.z; b[np][1] = q.w; b[np][2] = q.x; b[np][3] = q.y; }
            else               { b[np][0] = q.x; b[np][1] = q.y; b[np][2] = q.z; b[np][3] = q.w; }
        }
#pragma unroll
        for (int mt = 0; mt < 4; mt++)
#pragma unroll
            for (int np = 0; np < 2; np++) {
                unsigned b0[2] = {b[np][0], b[np][2]};
                unsigned b1[2] = {b[np][1], b[np][3]};
                mma_tf32(acc[mt][2 * np],     a[mt], b0);
                mma_tf32(acc[mt][2 * np + 1], a[mt], b1);
            }
    }
}

#define ACC_INIT float acc[4][4][4]; \
    _Pragma("unroll") for (int _a = 0; _a < 4; _a++) \
    _Pragma("unroll") for (int _b = 0; _b < 4; _b++) \
    _Pragma("unroll") for (int _c = 0; _c < 4; _c++) acc[_a][_b][_c] = 0.f;

#define PREP_OFFS int oA[4], oB[2]; \
    _Pragma("unroll") for (int _m = 0; _m < 4; _m++) { \
        int _l = (lane & 28) | ((lane ^ (lane >> 3) ^ _m) & 3); \
        oA[_m] = (wm * 4 + _m) * 256 + _l * 4; } \
    _Pragma("unroll") for (int _n = 0; _n < 2; _n++) { \
        int _l = (lane & 28) | ((lane ^ (lane >> 3) ^ ((wn & 1) * 2 + _n)) & 3); \
        oB[_n] = (wn * 2 + _n) * 256 + _l * 4; }

// 3-stage cp.async pipeline over pre-staged F-tiles.
__device__ __forceinline__ void gemm_f(const unsigned* __restrict__ A,
                                       const unsigned* __restrict__ B,
                                       int nk, int t, float (*acc)[4][4],
                                       unsigned* SA, unsigned* SB,
                                       const int* oA, const int* oB) {
    const int w8 = t * 8;
#pragma unroll
    for (int s = 0; s < 2; s++) {
        if (s < nk) {
            const unsigned* As = A + s * 2048 + w8;
            const unsigned* Bs = B + s * 2048 + w8;
            unsigned* sa = SA + s * 2048 + w8;
            unsigned* sb = SB + s * 2048 + w8;
            cp_async16(sa, As); cp_async16(sa + 4, As + 4);
            cp_async16(sb, Bs); cp_async16(sb + 4, Bs + 4);
        }
        cp_commit();
    }
    int buf = 0;
    for (int c = 0; c < nk; c++) {
        cp_wait1();
        __syncthreads();
        if (c + 2 < nk) {
            int nb = buf + 2; if (nb >= 3) nb -= 3;
            const unsigned* An = A + (c + 2) * 2048 + w8;
            const unsigned* Bn = B + (c + 2) * 2048 + w8;
            unsigned* sa = SA + nb * 2048 + w8;
            unsigned* sb = SB + nb * 2048 + w8;
            cp_async16(sa, An); cp_async16(sa + 4, An + 4);
            cp_async16(sb, Bn); cp_async16(sb + 4, Bn + 4);
        }
        cp_commit();
        compute16(SA + buf * 2048, SB + buf * 2048, acc, oA, oB);
        if (++buf == 3) buf = 0;
    }
    __syncthreads();
}

// -------------------- Kernel 0: convert x / W's into F-layout tf32 --------------------
__global__ __launch_bounds__(256)
void k_prep(const float* __restrict__ x,
            const float* __restrict__ Wq, const float* __restrict__ Wk,
            const float* __restrict__ Wv, const float* __restrict__ Wo) {
    const int bb = blockIdx.x;
    const float* src;
    unsigned* dst;
    int row0, k0;
    if (bb < 18432) {                       // x: mtile(384) x kc(48)
        int mtile = bb / 48, kc = bb - mtile * 48;
        src = x; row0 = mtile * 128; k0 = kc * 16;
        dst = g_x_f + (size_t)bb * 2048;
    } else {                                // W: z(4) x ntile(6) x kc(48)
        int b2 = bb - 18432;
        int z = b2 / 288, rem = b2 - z * 288;
        int ntile = rem / 48, kc = rem - ntile * 48;
        src = (z == 0) ? Wq : (z == 1) ? Wk : (z == 2) ? Wv : Wo;
        row0 = ntile * 128; k0 = kc * 16;
        dst = g_w_f + (size_t)b2 * 2048;
    }
    const int t = threadIdx.x;
    const int row = t >> 1, kt = t & 1;
    const float* p = src + (size_t)(row0 + row) * 768 + k0 + kt * 8;
    float4 f0 = *(const float4*)p, f1 = *(const float4*)(p + 4);
    const int t16 = row >> 4, r8 = (row >> 3) & 1, lr = row & 7;
    const int base = (t16 * 2 + kt) * 128;
    const int vx = ((kt ^ (t16 & 1)) & 1) << 1;
    const float e0[4] = {f0.x, f0.y, f0.z, f0.w};
    const float e1[4] = {f1.x, f1.y, f1.z, f1.w};
#pragma unroll
    for (int j = 0; j < 4; j++) {
        int lane = lr * 4 + ((j ^ (lr >> 1) ^ t16) & 3);
        dst[base + lane * 4 + ((0 + r8) ^ vx)] = f2tf(e0[j]);
        dst[base + lane * 4 + ((2 + r8) ^ vx)] = f2tf(e1[j]);
    }
}

// -------------------- Kernel 1: fused QKV projection --------------------
__global__ __launch_bounds__(256, 2)
void k_qkv(const float* __restrict__ bq, const float* __restrict__ bk,
           const float* __restrict__ bv) {
    const int z = blockIdx.x;
    const float* bias = (z == 0) ? bq : (z == 1) ? bk : bv;
    unsigned* out     = (z == 0) ? g_q_f : (z == 1) ? g_k_f : g_v_f;
    const float scale = (z == 0) ? 0.03125f : 1.0f;

    __shared__ unsigned SA[3 * 2048];
    __shared__ unsigned SB[3 * 2048];

    const int t = threadIdx.x;
    const int lane = t & 31, warp = t >> 5, wm = warp >> 2, wn = warp & 3;
    const int n0 = blockIdx.y * 128;
    const int m0 = blockIdx.z * 128;

    const unsigned* A = g_x_f + (size_t)blockIdx.z * 48 * 2048;
    const unsigned* B = g_w_f + (size_t)((z * 6 + blockIdx.y) * 48) * 2048;

    PREP_OFFS
    ACC_INIT
    gemm_f(A, B, 48, t, acc, SA, SB, oA, oB);

#pragma unroll
    for (int mt = 0; mt < 4; mt++)
#pragma unroll
        for (int nt = 0; nt < 4; nt++)
#pragma unroll
            for (int e = 0; e < 4; e++) {
                int m = m0 + wm * 64 + mt * 16 + (lane >> 2) + ((e >= 2) ? 8 : 0);
                int n = n0 + wn * 32 + nt * 8 + 2 * (lane & 3) + (e & 1);
                int r = m / 3072;
                int rem = m - r * 3072;
                int i = rem / 12;
                int nb = rem - i * 12;
                int h = n >> 6, d = n & 63;
                int hn = h * 12 + nb;
                unsigned w = f2tf((acc[mt][nt][e] + bias[n]) * scale);
                size_t idx;
                if (z < 2)   // q/k: rows=i, k=rd
                    idx = ((size_t)(hn * 2 + (i >> 7)) * 64 + (r * 4 + (d >> 4))) * 2048
                        + fword(i & 127, d & 15);
                else         // v: rows=rd, k=i
                    idx = ((size_t)(hn * 8 + (r >> 1)) * 16 + (i >> 4)) * 2048
                        + fword(((r & 1) << 6) | d, i & 15);
                out[idx] = w;
            }
}

// -------------------- Kernel 2: attention scores --------------------
__global__ __launch_bounds__(256, 2)
void k_scores() {
    const int hn = blockIdx.z;
    const unsigned* A = g_q_f + (size_t)(hn * 2 + blockIdx.x) * 64 * 2048;
    const unsigned* B = g_k_f + (size_t)(hn * 2 + blockIdx.y) * 64 * 2048;

    __shared__ unsigned SA[3 * 2048];
    __shared__ unsigned SB[3 * 2048];

    const int t = threadIdx.x;
    const int lane = t & 31, warp = t >> 5, wm = warp >> 2, wn = warp & 3;
    const int m0 = blockIdx.x * 128;
    const int n0 = blockIdx.y * 128;

    PREP_OFFS
    ACC_INIT
    gemm_f(A, B, 64, t, acc, SA, SB, oA, oB);

#pragma unroll
    for (int mt = 0; mt < 4; mt++)
#pragma unroll
        for (int nt = 0; nt < 4; nt++)
#pragma unroll
            for (int e = 0; e < 4; e++) {
                int m = m0 + wm * 64 + mt * 16 + (lane >> 2) + ((e >= 2) ? 8 : 0);
                int n = n0 + wn * 32 + nt * 8 + 2 * (lane & 3) + (e & 1);
                g_s[((size_t)hn << 16) + m * 256 + n] = acc[mt][nt][e];
            }
}

// -------------------- Kernel 3: bias + softmax --------------------
__global__ __launch_bounds__(256)
void k_softmax(const int* __restrict__ dist, const float* __restrict__ rb,
               float* __restrict__ probs_out) {
    const int bx = blockIdx.x;
    const int hn = bx >> 8;
    const int i = bx & 255;
    const int h = hn / 12;
    const int nb = hn - h * 12;
    const int j = threadIdx.x;
    const int lane = j & 31, warp = j >> 5;

    const size_t sidx = ((size_t)hn << 16) + (i << 8) + j;
    float s = g_s[sidx];

    int dd = dist[((h << 8) + i) * 256 + j];
    int a = dd < 0 ? -dd : dd;
    int bucket;
    if (a < 16) {
        bucket = a;
    } else {
        float nf = (float)a;
        float v = logf(nf * 0.0625f) / 8.047189562170502f * 15.0f;
        bucket = 16 + (int)v;
        if (bucket > 31) bucket = 31;
    }
    s += rb[bucket * 12 + nb];

    __shared__ float red[8];
    float m = s;
#pragma unroll
    for (int o = 16; o > 0; o >>= 1)
        m = fmaxf(m, __shfl_xor_sync(0xffffffffu, m, o));
    if (lane == 0) red[warp] = m;
    __syncthreads();
    float mx = red[0];
#pragma unroll
    for (int w = 1; w < 8; w++) mx = fmaxf(mx, red[w]);
    __syncthreads();

    const float e = expf(s - mx);
    float sum = e;
#pragma unroll
    for (int o = 16; o > 0; o >>= 1)
        sum += __shfl_xor_sync(0xffffffffu, sum, o);
    if (lane == 0) red[warp] = sum;
    __syncthreads();
    float tot = red[0];
#pragma unroll
    for (int w = 1; w < 8; w++) tot += red[w];

    const float p = e / tot;
    if (probs_out) probs_out[sidx] = p;
    g_p_f[((size_t)(hn * 2 + (i >> 7)) * 16 + (j >> 4)) * 2048 + fword(i & 127, j & 15)] = f2tf(p);
}

// -------------------- Kernel 4: context --------------------
__global__ __launch_bounds__(256, 2)
void k_ctx() {
    const int hn = blockIdx.z;
    const unsigned* A = g_p_f + (size_t)(hn * 2 + blockIdx.x) * 16 * 2048;
    const unsigned* B = g_v_f + (size_t)(hn * 8 + blockIdx.y) * 16 * 2048;

    __shared__ unsigned SA[3 * 2048];
    __shared__ unsigned SB[3 * 2048];

    const int t = threadIdx.x;
    const int lane = t & 31, warp = t >> 5, wm = warp >> 2, wn = warp & 3;
    const int m0 = blockIdx.x * 128;   // i
    const int n0 = blockIdx.y * 128;   // rd

    PREP_OFFS
    ACC_INIT
    gemm_f(A, B, 16, t, acc, SA, SB, oA, oB);

    const int h = hn / 12;
    const int nb = hn - h * 12;
#pragma unroll
    for (int mt = 0; mt < 4; mt++)
#pragma unroll
        for (int nt = 0; nt < 4; nt++)
#pragma unroll
            for (int e = 0; e < 4; e++) {
                int i = m0 + wm * 64 + mt * 16 + (lane >> 2) + ((e >= 2) ? 8 : 0);
                int n = n0 + wn * 32 + nt * 8 + 2 * (lane & 3) + (e & 1);  // rd
                int r = n >> 6, d = n & 63;
                int mo = (r * 256 + i) * 12 + nb;
                int ec = h * 64 + d;
                g_ctx_f[((size_t)(mo >> 7) * 48 + (ec >> 4)) * 2048 + fword(mo & 127, d & 15)]
                    = f2tf(acc[mt][nt][e]);
            }
}

// -------------------- Kernel 5: output projection --------------------
__global__ __launch_bounds__(256, 2)
void k_out(const float* __restrict__ bo, float* __restrict__ out) {
    __shared__ unsigned SA[3 * 2048];
    __shared__ unsigned SB[3 * 2048];

    const int t = threadIdx.x;
    const int lane = t & 31, warp = t >> 5, wm = warp >> 2, wn = warp & 3;
    const int n0 = blockIdx.x * 128;
    const int m0 = blockIdx.y * 128;

    const unsigned* A = g_ctx_f + (size_t)blockIdx.y * 48 * 2048;
    const unsigned* B = g_w_f + (size_t)((3 * 6 + blockIdx.x) * 48) * 2048;

    PREP_OFFS
    ACC_INIT
    gemm_f(A, B, 48, t, acc, SA, SB, oA, oB);

#pragma unroll
    for (int mt = 0; mt < 4; mt++)
#pragma unroll
        for (int nt = 0; nt < 4; nt++)
#pragma unroll
            for (int e = 0; e < 4; e++) {
                int m = m0 + wm * 64 + mt * 16 + (lane >> 2) + ((e >= 2) ? 8 : 0);
                int n = n0 + wn * 32 + nt * 8 + 2 * (lane & 3) + (e & 1);
                out[(size_t)m * 768 + n] = acc[mt][nt][e] + bo[n];
            }
}

// -------------------- launch --------------------
extern "C" void kernel_launch(void* const* d_in, const int* in_sizes, int n_in,
                              void* d_out, int out_size) {
    const float* x    = (const float*)d_in[0];
    const int*   dist = (const int*)d_in[1];
    const float* Wq   = (const float*)d_in[2];
    const float* bq   = (const float*)d_in[3];
    const float* Wk   = (const float*)d_in[4];
    const float* bk   = (const float*)d_in[5];
    const float* Wv   = (const float*)d_in[6];
    const float* bv   = (const float*)d_in[7];
    const float* Wo   = (const float*)d_in[8];
    const float* bo   = (const float*)d_in[9];
    const float* rb   = (const float*)d_in[10];

    float* out = (float*)d_out;
    float* probs = (out_size >= OUT_ELEMS + PROBS_ELEMS) ? (out + OUT_ELEMS) : nullptr;

    dim3 thr(256);
    k_prep<<<dim3(18432 + 1152), thr>>>(x, Wq, Wk, Wv, Wo);
    k_qkv<<<dim3(3, 6, 384), thr>>>(bq, bk, bv);
    k_scores<<<dim3(2, 2, HN), thr>>>();
    k_softmax<<<dim3(HN * 256), thr>>>(dist, rb, probs);
    k_ctx<<<dim3(2, 8, HN), thr>>>();
    k_out<<<dim3(6, 384), thr>>>(bo, out);
}